// round 1
// baseline (speedup 1.0000x reference)
#include <cuda_runtime.h>

#define NFIELDS 32
#define EMBED   64
#define NPAIRS  496
#define BATCH   2048
#define EMB_ROW (NFIELDS * EMBED)   // 2048 floats per batch row
#define KER_ROW (NPAIRS * EMBED)    // 31744 floats per i row

#define BM      128                 // batches per block
#define JSTAGE  32                  // j values staged in smem at once
#define KSTR    68                  // sK row stride (floats): 16B aligned, conflict-free writes
#define PSTR    128                 // sP row stride (floats): swizzled

__device__ __forceinline__ unsigned long long pack2(float x, float y) {
    unsigned long long r;
    asm("mov.b64 %0, {%1, %2};" : "=l"(r) : "f"(x), "f"(y));
    return r;
}
__device__ __forceinline__ void unpack2(unsigned long long v, float& x, float& y) {
    asm("mov.b64 {%0, %1}, %2;" : "=f"(x), "=f"(y) : "l"(v));
}
__device__ __forceinline__ unsigned long long fma2(unsigned long long a,
                                                   unsigned long long b,
                                                   unsigned long long c) {
    unsigned long long d;
    asm("fma.rn.f32x2 %0, %1, %2, %3;" : "=l"(d) : "l"(a), "l"(b), "l"(c));
    return d;
}

// Block: 128 threads. tx = t&7 owns 8 consecutive i (= tx*8..tx*8+7),
// ty = t>>3 owns 8 consecutive batches (= ty*8..ty*8+7).
// acc[bb][ip] is an f32x2 pair over i: (i = tx*8+2*ip, i+1).
__global__ void __launch_bounds__(128, 3)
opn_kernel(const float* __restrict__ emb, const float* __restrict__ ker,
           float* __restrict__ out)
{
    __shared__ __align__(16) float sK[EMBED * KSTR];   // sK[j*KSTR + i] = K_p[i][j]
    __shared__ __align__(16) float sP[JSTAGE * PSTR];  // swizzled [jj][b]

    const int t  = threadIdx.x;
    const int tx = t & 7;
    const int ty = t >> 3;
    const int p  = blockIdx.y;
    const int batch_base = blockIdx.x * BM;

    // decode pair index -> (r, c) of triu_indices(32, k=1)
    int r = 0, rem = p;
    while (rem >= (NFIELDS - 1 - r)) { rem -= (NFIELDS - 1 - r); ++r; }
    const int c = r + 1 + rem;

    // ---- load K_p transposed into smem: sK[j][i] = ker[i, p, j] ----
    {
        const float* kp = ker + (size_t)p * EMBED;
        #pragma unroll
        for (int it = 0; it < 32; ++it) {
            int idx = it * 128 + t;          // 0..4095
            int i = idx >> 6;
            int j = idx & 63;
            sK[j * KSTR + i] = kp[(size_t)i * KER_ROW + j];
        }
    }

    unsigned long long acc[8][4];
    #pragma unroll
    for (int bb = 0; bb < 8; ++bb)
        #pragma unroll
        for (int ip = 0; ip < 4; ++ip)
            acc[bb][ip] = 0ull;   // bit pattern of (0.f, 0.f)

    const float* Pbase = emb + (size_t)batch_base * EMB_ROW + (size_t)r * EMBED;

    #pragma unroll 1
    for (int stage = 0; stage < 2; ++stage) {
        const int jbase = stage * JSTAGE;

        __syncthreads();   // also orders the sK stores before first-stage reads

        // ---- stage P: sP[jj][swz(b)] = emb[b, r, jbase+jj] ----
        #pragma unroll
        for (int it = 0; it < 8; ++it) {
            int idx4 = it * 128 + t;         // 0..1023 float4 slots
            int b  = idx4 >> 3;              // 0..127
            int j4 = idx4 & 7;               // 0..7  -> j = jbase + j4*4 + u
            float4 v = *(const float4*)(Pbase + (size_t)b * EMB_ROW + jbase + j4 * 4);
            int hh = (((jbase >> 2) + j4) & 7);             // = (j>>2)&7 for all 4 u
            int cb = ((((b >> 2) ^ hh) << 2) | (b & 3));    // swizzled column
            int row = j4 * 4;
            sP[(row + 0) * PSTR + cb] = v.x;
            sP[(row + 1) * PSTR + cb] = v.y;
            sP[(row + 2) * PSTR + cb] = v.z;
            sP[(row + 3) * PSTR + cb] = v.w;
        }
        __syncthreads();

        // ---- main loop over j in this stage ----
        #pragma unroll 4
        for (int jj = 0; jj < JSTAGE; ++jj) {
            const int j = jbase + jj;

            // K pairs for this thread's 8 i values (free f32x2 packing)
            const ulonglong2* pa = (const ulonglong2*)&sK[j * KSTR + tx * 8];
            ulonglong2 a01 = pa[0];
            ulonglong2 a23 = pa[1];
            unsigned long long aK[4] = { a01.x, a01.y, a23.x, a23.y };

            // P values for this thread's 8 batches (de-swizzled)
            const int h = (j >> 2) & 7;
            const float4* pb = (const float4*)&sP[jj * PSTR];
            float4 b0 = pb[(2 * ty)     ^ h];   // b = ty*8 + 0..3
            float4 b1 = pb[(2 * ty + 1) ^ h];   // b = ty*8 + 4..7

            unsigned long long bd[8];
            bd[0] = pack2(b0.x, b0.x); bd[1] = pack2(b0.y, b0.y);
            bd[2] = pack2(b0.z, b0.z); bd[3] = pack2(b0.w, b0.w);
            bd[4] = pack2(b1.x, b1.x); bd[5] = pack2(b1.y, b1.y);
            bd[6] = pack2(b1.z, b1.z); bd[7] = pack2(b1.w, b1.w);

            #pragma unroll
            for (int bb = 0; bb < 8; ++bb)
                #pragma unroll
                for (int ip = 0; ip < 4; ++ip)
                    acc[bb][ip] = fma2(bd[bb], aK[ip], acc[bb][ip]);
        }
    }

    // ---- epilogue: dot with q = emb[b, c, :], reduce over i (tx lanes) ----
    #pragma unroll
    for (int bb = 0; bb < 8; ++bb) {
        const int b = batch_base + ty * 8 + bb;
        const float* q = emb + (size_t)b * EMB_ROW + (size_t)c * EMBED + tx * 8;
        float4 q0 = *(const float4*)q;
        float4 q1 = *(const float4*)(q + 4);

        float s = 0.f, lo, hi;
        unpack2(acc[bb][0], lo, hi); s += lo * q0.x + hi * q0.y;
        unpack2(acc[bb][1], lo, hi); s += lo * q0.z + hi * q0.w;
        unpack2(acc[bb][2], lo, hi); s += lo * q1.x + hi * q1.y;
        unpack2(acc[bb][3], lo, hi); s += lo * q1.z + hi * q1.w;

        // lanes with same ty differ only in low 3 bits (tx)
        s += __shfl_xor_sync(0xffffffffu, s, 1);
        s += __shfl_xor_sync(0xffffffffu, s, 2);
        s += __shfl_xor_sync(0xffffffffu, s, 4);

        if (tx == 0)
            out[(size_t)b * NPAIRS + p] = s;
    }
}

extern "C" void kernel_launch(void* const* d_in, const int* in_sizes, int n_in,
                              void* d_out, int out_size) {
    const float* emb = (const float*)d_in[0];   // (2048, 32, 64) f32
    const float* ker = (const float*)d_in[1];   // (64, 496, 64) f32
    float* out = (float*)d_out;                 // (2048, 1, 496) f32
    (void)in_sizes; (void)n_in; (void)out_size;

    dim3 grid(BATCH / BM, NPAIRS);
    dim3 block(128);
    opn_kernel<<<grid, block>>>(emb, ker, out);
}

// round 3
// speedup vs baseline: 1.2997x; 1.2997x over previous
#include <cuda_runtime.h>
#include <cstdint>

#define NFIELDS 32
#define EMBED   64
#define NPAIRS  496
#define BATCH   2048
#define EMB_ROW (NFIELDS * EMBED)   // 2048 floats per batch
#define KER_ROW (NPAIRS * EMBED)    // 31744 floats per i row

#define BM 128                       // batches per block (M tile)

__device__ __forceinline__ uint32_t f2tf32(float x) {
    uint32_t r;
    asm("cvt.rna.tf32.f32 %0, %1;" : "=r"(r) : "f"(x));
    return r;
}

__device__ __forceinline__ void mma_tf32(float* d, uint32_t a0, uint32_t a1,
                                         uint32_t a2, uint32_t a3,
                                         uint32_t b0, uint32_t b1) {
    asm("mma.sync.aligned.m16n8k8.row.col.f32.tf32.tf32.f32 "
        "{%0,%1,%2,%3}, {%4,%5,%6,%7}, {%8,%9}, {%0,%1,%2,%3};"
        : "+f"(d[0]), "+f"(d[1]), "+f"(d[2]), "+f"(d[3])
        : "r"(a0), "r"(a1), "r"(a2), "r"(a3), "r"(b0), "r"(b1));
}

// Fragment-layout staging:
//   sAfrag[kt][mt][lane] = float4 {a0,a1,a2,a3} for mma tile (mt, kt)
//     a0 = P[mt*16 + lane/4][kt*8 + lane%4]       a1 = P[row+8][k]
//     a2 = P[row][k+4]                            a3 = P[row+8][k+4]
//   sBfrag[kt][nt][lane] = float2 {b0,b1}
//     b0 = Kp[nt*8 + lane/4][kt*8 + lane%4]       b1 = Kp[n][k+4]
__global__ void __launch_bounds__(128, 2)
opn_mma_kernel(const float* __restrict__ emb, const float* __restrict__ ker,
               float* __restrict__ out)
{
    __shared__ __align__(16) uint4  sAfrag[8 * 8 * 32];   // 32 KB
    __shared__ __align__(16) uint2  sBfrag[8 * 8 * 32];   // 16 KB

    const int t    = threadIdx.x;
    const int w    = t >> 5;
    const int lane = t & 31;
    const int p    = blockIdx.y;
    const int batch_base = blockIdx.x * BM;

    // decode pair index -> (r, c) of triu_indices(32, k=1)
    int r = 0, rem = p;
    while (rem >= (NFIELDS - 1 - r)) { rem -= (NFIELDS - 1 - r); ++r; }
    const int c = r + 1 + rem;

    const float* Pb = emb + (size_t)batch_base * EMB_ROW + (size_t)r * EMBED;
    const float* Kb = ker + (size_t)p * EMBED;

    // ---- stage A fragments (each P element read exactly once) ----
    #pragma unroll
    for (int it = 0; it < 16; ++it) {
        int idx = it * 128 + t;            // 0..2047 fragment slots
        int l   = idx & 31;
        int mt  = (idx >> 5) & 7;
        int kt  = idx >> 8;
        int b   = mt * 16 + (l >> 2);
        int j   = kt * 8 + (l & 3);
        const float* row0 = Pb + (size_t)b * EMB_ROW + j;
        const float* row1 = row0 + 8 * EMB_ROW;
        uint4 f;
        f.x = f2tf32(row0[0]);
        f.y = f2tf32(row1[0]);
        f.z = f2tf32(row0[4]);
        f.w = f2tf32(row1[4]);
        sAfrag[idx] = f;
    }
    // ---- stage B fragments ----
    #pragma unroll
    for (int it = 0; it < 16; ++it) {
        int idx = it * 128 + t;            // 0..2047
        int l   = idx & 31;
        int nt  = (idx >> 5) & 7;
        int kt  = idx >> 8;
        int n   = nt * 8 + (l >> 2);
        int k   = kt * 8 + (l & 3);
        const float* src = Kb + (size_t)n * KER_ROW + k;
        uint2 f;
        f.x = f2tf32(src[0]);
        f.y = f2tf32(src[4]);
        sBfrag[idx] = f;
    }
    __syncthreads();

    // ---- main loop: per k-step, 2 LDS.128 + 8 LDS.64 + 16 HMMA ----
    float acc[2][8][4];
    #pragma unroll
    for (int mm = 0; mm < 2; ++mm)
        #pragma unroll
        for (int nt = 0; nt < 8; ++nt)
            #pragma unroll
            for (int u = 0; u < 4; ++u)
                acc[mm][nt][u] = 0.f;

    #pragma unroll
    for (int kt = 0; kt < 8; ++kt) {
        uint4 A[2];
        #pragma unroll
        for (int mm = 0; mm < 2; ++mm)
            A[mm] = sAfrag[(kt * 8 + (w * 2 + mm)) * 32 + lane];
        uint2 B[8];
        #pragma unroll
        for (int nt = 0; nt < 8; ++nt)
            B[nt] = sBfrag[(kt * 8 + nt) * 32 + lane];

        #pragma unroll
        for (int mm = 0; mm < 2; ++mm)
            #pragma unroll
            for (int nt = 0; nt < 8; ++nt)
                mma_tf32(acc[mm][nt], A[mm].x, A[mm].y, A[mm].z, A[mm].w,
                         B[nt].x, B[nt].y);
    }

    // ---- epilogue: dot with q = emb[b, c, :], reduce over the N (=i) dim ----
    #pragma unroll
    for (int mm = 0; mm < 2; ++mm) {
        const int row0 = (w * 2 + mm) * 16 + (lane >> 2);
        const int gb0  = batch_base + row0;
        const int gb1  = gb0 + 8;
        const float* q0 = emb + (size_t)gb0 * EMB_ROW + (size_t)c * EMBED;
        const float* q1 = emb + (size_t)gb1 * EMB_ROW + (size_t)c * EMBED;

        float s0 = 0.f, s1 = 0.f;
        #pragma unroll
        for (int nt = 0; nt < 8; ++nt) {
            const int col0 = nt * 8 + (lane & 3) * 2;
            float2 qv0 = *(const float2*)(q0 + col0);
            float2 qv1 = *(const float2*)(q1 + col0);
            s0 += acc[mm][nt][0] * qv0.x + acc[mm][nt][1] * qv0.y;
            s1 += acc[mm][nt][2] * qv1.x + acc[mm][nt][3] * qv1.y;
        }
        // reduce over the 4 lanes sharing the same row (lane & 3)
        s0 += __shfl_xor_sync(0xffffffffu, s0, 1);
        s0 += __shfl_xor_sync(0xffffffffu, s0, 2);
        s1 += __shfl_xor_sync(0xffffffffu, s1, 1);
        s1 += __shfl_xor_sync(0xffffffffu, s1, 2);

        if ((lane & 3) == 0) {
            out[(size_t)gb0 * NPAIRS + p] = s0;
            out[(size_t)gb1 * NPAIRS + p] = s1;
        }
    }
}

extern "C" void kernel_launch(void* const* d_in, const int* in_sizes, int n_in,
                              void* d_out, int out_size) {
    const float* emb = (const float*)d_in[0];   // (2048, 32, 64) f32
    const float* ker = (const float*)d_in[1];   // (64, 496, 64) f32
    float* out = (float*)d_out;                 // (2048, 1, 496) f32
    (void)in_sizes; (void)n_in; (void)out_size;

    dim3 grid(BATCH / BM, NPAIRS);
    opn_mma_kernel<<<grid, 128>>>(emb, ker, out);
}

// round 4
// speedup vs baseline: 1.7181x; 1.3220x over previous
#include <cuda_runtime.h>
#include <cstdint>

#define NFIELDS 32
#define EMBED   64
#define NPAIRS  496
#define BATCH   2048
#define EMB_ROW (NFIELDS * EMBED)   // 2048 floats per batch
#define KER_ROW (NPAIRS * EMBED)    // 31744 floats per i row

#define BM      128                 // batches per block (M tile)
#define PCHUNK  8                   // pairs per block (all share one r)
#define NCHUNKS 76                  // sum over r of ceil((31-r)/8)

__device__ __forceinline__ uint32_t f2tf32(float x) {
    uint32_t r;
    asm("cvt.rna.tf32.f32 %0, %1;" : "=r"(r) : "f"(x));
    return r;
}

__device__ __forceinline__ void mma_tf32(float* d, uint32_t a0, uint32_t a1,
                                         uint32_t a2, uint32_t a3,
                                         uint32_t b0, uint32_t b1) {
    asm("mma.sync.aligned.m16n8k8.row.col.f32.tf32.tf32.f32 "
        "{%0,%1,%2,%3}, {%4,%5,%6,%7}, {%8,%9}, {%0,%1,%2,%3};"
        : "+f"(d[0]), "+f"(d[1]), "+f"(d[2]), "+f"(d[3])
        : "r"(a0), "r"(a1), "r"(a2), "r"(a3), "r"(b0), "r"(b1));
}

// Stage K_p fragments: sB[(kt*8+nt)*32 + lane] = {Kp[n][k], Kp[n][k+4]},
// n = nt*8 + lane/4, k = kt*8 + lane%4.
__device__ __forceinline__ void stage_B(uint2* __restrict__ sB,
                                        const float* __restrict__ Kb, int t) {
    #pragma unroll
    for (int it = 0; it < 16; ++it) {
        int idx = it * 128 + t;            // 0..2047
        int l   = idx & 31;
        int nt  = (idx >> 5) & 7;
        int kt  = idx >> 8;
        const float* src = Kb + (size_t)(nt * 8 + (l >> 2)) * KER_ROW + kt * 8 + (l & 3);
        uint2 f;
        f.x = f2tf32(src[0]);
        f.y = f2tf32(src[4]);
        sB[idx] = f;
    }
}

__global__ void __launch_bounds__(128, 2)
opn_mma_kernel(const float* __restrict__ emb, const float* __restrict__ ker,
               float* __restrict__ out)
{
    // dynamic smem: sA 2048*uint4 (32KB) | sB0 2048*uint2 (16KB) | sB1 (16KB)
    extern __shared__ __align__(16) uint4 dynsmem[];
    uint4* sAfrag = dynsmem;
    uint2* sB0 = (uint2*)(dynsmem + 2048);
    uint2* sB1 = sB0 + 2048;

    const int t    = threadIdx.x;
    const int w    = t >> 5;
    const int lane = t & 31;
    const int batch_base = blockIdx.x * BM;

    // ---- decode chunk id -> (r, first pair p0, #pairs np, first col c0) ----
    int cid = blockIdx.y, r = 0, pbase = 0;
    while (true) {
        int cnt = 31 - r;
        int nch = (cnt + PCHUNK - 1) >> 3;
        if (cid < nch) break;
        cid -= nch; pbase += cnt; ++r;
    }
    const int p0 = pbase + cid * PCHUNK;
    const int np = min(PCHUNK, (31 - r) - cid * PCHUNK);
    const int c0 = r + 1 + cid * PCHUNK;

    // ---- stage A fragments for P = emb[:, r, :] (once per block) ----
    //   sAfrag[(kt*8+mt)*32 + lane] = {P[m][k], P[m+8][k], P[m][k+4], P[m+8][k+4]},
    //   m = mt*16 + lane/4, k = kt*8 + lane%4.
    {
        const float* Pb = emb + (size_t)batch_base * EMB_ROW + (size_t)r * EMBED;
        #pragma unroll
        for (int it = 0; it < 16; ++it) {
            int idx = it * 128 + t;
            int l   = idx & 31;
            int mt  = (idx >> 5) & 7;
            int kt  = idx >> 8;
            const float* row0 = Pb + (size_t)(mt * 16 + (l >> 2)) * EMB_ROW + kt * 8 + (l & 3);
            const float* row1 = row0 + 8 * EMB_ROW;
            uint4 f;
            f.x = f2tf32(row0[0]);
            f.y = f2tf32(row1[0]);
            f.z = f2tf32(row0[4]);
            f.w = f2tf32(row1[4]);
            sAfrag[idx] = f;
        }
    }
    // ---- stage B for first pair ----
    stage_B(sB0, ker + (size_t)p0 * EMBED, t);
    __syncthreads();

    // ---- pair loop: MMA + fused epilogue, double-buffered B ----
    for (int k = 0; k < np; ++k) {
        uint2* sBc = (k & 1) ? sB1 : sB0;
        uint2* sBn = (k & 1) ? sB0 : sB1;

        // prefetch next pair's K fragments (overlaps with MMA + epilogue)
        if (k + 1 < np)
            stage_B(sBn, ker + (size_t)(p0 + k + 1) * EMBED, t);

        float acc[2][8][4];
        #pragma unroll
        for (int mm = 0; mm < 2; ++mm)
            #pragma unroll
            for (int nt = 0; nt < 8; ++nt)
                #pragma unroll
                for (int u = 0; u < 4; ++u)
                    acc[mm][nt][u] = 0.f;

        #pragma unroll
        for (int kt = 0; kt < 8; ++kt) {
            uint4 A[2];
            #pragma unroll
            for (int mm = 0; mm < 2; ++mm)
                A[mm] = sAfrag[(kt * 8 + (w * 2 + mm)) * 32 + lane];
            uint2 B[8];
            #pragma unroll
            for (int nt = 0; nt < 8; ++nt)
                B[nt] = sBc[(kt * 8 + nt) * 32 + lane];

            #pragma unroll
            for (int mm = 0; mm < 2; ++mm)
                #pragma unroll
                for (int nt = 0; nt < 8; ++nt)
                    mma_tf32(acc[mm][nt], A[mm].x, A[mm].y, A[mm].z, A[mm].w,
                             B[nt].x, B[nt].y);
        }

        // ---- epilogue: dot with q = emb[b, c, :], reduce over i ----
        const int c = c0 + k;
        const int p = p0 + k;
        #pragma unroll
        for (int mm = 0; mm < 2; ++mm) {
            const int row0 = (w * 2 + mm) * 16 + (lane >> 2);
            const int gb0  = batch_base + row0;
            const int gb1  = gb0 + 8;
            const float* q0 = emb + (size_t)gb0 * EMB_ROW + (size_t)c * EMBED;
            const float* q1 = emb + (size_t)gb1 * EMB_ROW + (size_t)c * EMBED;

            float s0 = 0.f, s1 = 0.f;
            #pragma unroll
            for (int nt = 0; nt < 8; ++nt) {
                const int col0 = nt * 8 + (lane & 3) * 2;
                float2 qv0 = *(const float2*)(q0 + col0);
                float2 qv1 = *(const float2*)(q1 + col0);
                s0 += acc[mm][nt][0] * qv0.x + acc[mm][nt][1] * qv0.y;
                s1 += acc[mm][nt][2] * qv1.x + acc[mm][nt][3] * qv1.y;
            }
            s0 += __shfl_xor_sync(0xffffffffu, s0, 1);
            s0 += __shfl_xor_sync(0xffffffffu, s0, 2);
            s1 += __shfl_xor_sync(0xffffffffu, s1, 1);
            s1 += __shfl_xor_sync(0xffffffffu, s1, 2);

            if ((lane & 3) == 0) {
                out[(size_t)gb0 * NPAIRS + p] = s0;
                out[(size_t)gb1 * NPAIRS + p] = s1;
            }
        }
        __syncthreads();   // sBn writes visible before next iter reads it
    }
}

#define SMEM_TOTAL (2048 * 16 + 2 * 2048 * 8)   // 64 KB

extern "C" void kernel_launch(void* const* d_in, const int* in_sizes, int n_in,
                              void* d_out, int out_size) {
    const float* emb = (const float*)d_in[0];   // (2048, 32, 64) f32
    const float* ker = (const float*)d_in[1];   // (64, 496, 64) f32
    float* out = (float*)d_out;                 // (2048, 1, 496) f32
    (void)in_sizes; (void)n_in; (void)out_size;

    static bool attr_set = false;
    if (!attr_set) {
        cudaFuncSetAttribute(opn_mma_kernel,
                             cudaFuncAttributeMaxDynamicSharedMemorySize, SMEM_TOTAL);
        attr_set = true;
    }
    dim3 grid(BATCH / BM, NCHUNKS);
    opn_mma_kernel<<<grid, 128, SMEM_TOTAL>>>(emb, ker, out);
}